// round 14
// baseline (speedup 1.0000x reference)
#include <cuda_runtime.h>

#define BB 8
#define HH 8
#define NN 4096
#define DD 64
#define MM 64
#define TS 66          // 64-wide row stride (float2 aligned)
#define ATS 68         // transposed-A stride, float4 aligned
#define ITS 36         // 32-wide row stride, float4 aligned
#define PS3 2312       // sim3 plane: 64*36+8
#define PS1T 2308      // sim1 transposed plane: 64*36+4 (16B-aligned)
#define NP 32          // spart partials per (b,k)

// ---------------- scratch ----------------
__device__ float g_ql[BB*HH*MM*DD];
__device__ float g_kl[BB*HH*MM*DD];
__device__ float g_s2raw[BB*HH*MM*MM];
__device__ float g_attn2[BB*HH*MM*MM];
__device__ float g_zinv[BB*HH*MM*MM];
__device__ float g_T2[BB*HH*MM*MM];
__device__ float g_Sp[(size_t)BB*HH*NP*MM*DD];
__device__ float g_M[BB*HH*MM*DD];
__device__ float g_G3a[(size_t)BB*HH*MM*NN];
__device__ float g_G3b[(size_t)BB*HH*MM*NN];
__device__ float g_stats[BB*HH*MM*2];
__device__ unsigned int g_maxcol_u, g_maxrow_u;

__device__ __forceinline__ void ffma2(float2& a, float b, const float2 c) {
    float2 bb = make_float2(b, b);
    asm("fma.rn.f32x2 %0, %1, %2, %0;"
        : "+l"(reinterpret_cast<unsigned long long&>(a))
        : "l"(reinterpret_cast<const unsigned long long&>(bb)),
          "l"(reinterpret_cast<const unsigned long long&>(c)));
}

template<int L, int AS>
__device__ __forceinline__ void mmstd(const float* __restrict__ A, const float* __restrict__ B,
                                      float2 R[8], int ig, int jg) {
    #pragma unroll
    for (int u = 0; u < 8; u++) R[u] = make_float2(0.f, 0.f);
    #pragma unroll 4
    for (int k = 0; k < L; k++) {
        float a0 = A[(ig     )*AS + k];
        float a1 = A[(ig + 16)*AS + k];
        float a2 = A[(ig + 32)*AS + k];
        float a3 = A[(ig + 48)*AS + k];
        float2 b0 = *(const float2*)&B[k*TS + 2*jg];
        float2 b1 = *(const float2*)&B[k*TS + 2*jg + 32];
        ffma2(R[0], a0, b0); ffma2(R[1], a0, b1);
        ffma2(R[2], a1, b0); ffma2(R[3], a1, b1);
        ffma2(R[4], a2, b0); ffma2(R[5], a2, b1);
        ffma2(R[6], a3, b0); ffma2(R[7], a3, b1);
    }
}
template<int L, int AS>
__device__ __forceinline__ void mmstd4(const float* __restrict__ At, const float* __restrict__ B,
                                       float2 R[8], int ig, int jg) {
    #pragma unroll
    for (int u = 0; u < 8; u++) R[u] = make_float2(0.f, 0.f);
    #pragma unroll 4
    for (int k = 0; k < L; k++) {
        float4 a = *(const float4*)&At[k*AS + 4*ig];
        float2 b0 = *(const float2*)&B[k*TS + 2*jg];
        float2 b1 = *(const float2*)&B[k*TS + 2*jg + 32];
        ffma2(R[0], a.x, b0); ffma2(R[1], a.x, b1);
        ffma2(R[2], a.y, b0); ffma2(R[3], a.y, b1);
        ffma2(R[4], a.z, b0); ffma2(R[5], a.z, b1);
        ffma2(R[6], a.w, b0); ffma2(R[7], a.w, b1);
    }
}
template<int S>
__device__ __forceinline__ void storeR(float* __restrict__ dst, const float2 R[8], int ig, int jg) {
    #pragma unroll
    for (int r = 0; r < 4; r++) {
        *(float2*)&dst[(size_t)(ig + 16*r)*S + 2*jg]      = R[2*r];
        *(float2*)&dst[(size_t)(ig + 16*r)*S + 2*jg + 32] = R[2*r + 1];
    }
}
template<int S>
__device__ __forceinline__ void storeR4(float* __restrict__ dst, const float2 R[8], int ig, int jg) {
    #pragma unroll
    for (int r = 0; r < 4; r++) {
        *(float2*)&dst[(size_t)(4*ig + r)*S + 2*jg]      = R[2*r];
        *(float2*)&dst[(size_t)(4*ig + r)*S + 2*jg + 32] = R[2*r + 1];
    }
}
template<int PSv>
__device__ __forceinline__ void mix8v(float* __restrict__ raw, const float* __restrict__ ws, int p) {
    float2 a[8];
    #pragma unroll
    for (int h = 0; h < 8; h++) a[h] = *(const float2*)&raw[h*PSv + p];
    #pragma unroll
    for (int kk = 0; kk < 8; kk++) {
        float2 s = make_float2(0.f, 0.f);
        #pragma unroll
        for (int h = 0; h < 8; h++) ffma2(s, ws[h*8 + kk], a[h]);
        *(float2*)&raw[kk*PSv + p] = s;
    }
}

// ---------------- K1: landmarks (+ atomic reset) ----------------
__global__ void __launch_bounds__(256) k_landmarks(const float* __restrict__ q, const float* __restrict__ k) {
    if (blockIdx.x == 0 && blockIdx.y == 0 && threadIdx.x == 0) {
        g_maxcol_u = 0u; g_maxrow_u = 0u;
    }
    int bh = blockIdx.x;
    int mi = blockIdx.y*4 + (threadIdx.x >> 6);
    int d  = threadIdx.x & 63;
    const float* qp = q + ((size_t)bh*NN + (size_t)mi*64)*DD + d;
    const float* kp = k + ((size_t)bh*NN + (size_t)mi*64)*DD + d;
    float sq = 0.f, sk = 0.f;
    #pragma unroll 8
    for (int t = 0; t < 64; t++) { sq += qp[(size_t)t*DD]; sk += kp[(size_t)t*DD]; }
    g_ql[(bh*MM + mi)*DD + d] = sq * (1.f/64.f);
    g_kl[(bh*MM + mi)*DD + d] = sk * (1.f/64.f);
}

// ---------------- K2a: sim2 raw dots, 512 threads ----------------
__global__ void __launch_bounds__(512) k_sim2dots() {
    __shared__ float qa[64*TS];
    __shared__ float kb[64*TS];
    int bh = blockIdx.x, t = threadIdx.x;
    const float* qsrc = g_ql + (size_t)bh*4096;
    const float* ksrc = g_kl + (size_t)bh*4096;
    for (int x = t; x < 4096; x += 512) {
        int i = x >> 6, d = x & 63;
        qa[i*TS + d] = qsrc[x];
        kb[d*TS + i] = ksrc[x];
    }
    __syncthreads();
    int ig = t >> 4, jg = t & 15;
    float2 R[4];
    #pragma unroll
    for (int u = 0; u < 4; u++) R[u] = make_float2(0.f, 0.f);
    #pragma unroll 4
    for (int k = 0; k < 64; k++) {
        float a0 = qa[(ig     )*TS + k];
        float a1 = qa[(ig + 32)*TS + k];
        float2 b0 = *(const float2*)&kb[k*TS + 2*jg];
        float2 b1 = *(const float2*)&kb[k*TS + 2*jg + 32];
        ffma2(R[0], a0, b0); ffma2(R[1], a0, b1);
        ffma2(R[2], a1, b0); ffma2(R[3], a1, b1);
    }
    float* dst = g_s2raw + (size_t)bh*4096;
    *(float2*)&dst[(ig     )*64 + 2*jg]      = R[0];
    *(float2*)&dst[(ig     )*64 + 2*jg + 32] = R[1];
    *(float2*)&dst[(ig + 32)*64 + 2*jg]      = R[2];
    *(float2*)&dst[(ig + 32)*64 + 2*jg + 32] = R[3];
}

// ---------------- K2b: mix + softmax + scale sums -> attn2, 512 threads ----------------
__global__ void __launch_bounds__(512) k_sim2mix(const float* __restrict__ W) {
    __shared__ float acc[64*TS];
    int b = blockIdx.x >> 3, kk = blockIdx.x & 7;
    int t = threadIdx.x;
    float w[8];
    #pragma unroll
    for (int h = 0; h < 8; h++) w[h] = __ldg(&W[h*8 + kk]);
    for (int x = t; x < 4096; x += 512) {
        float s = 0.f;
        #pragma unroll
        for (int h = 0; h < 8; h++) s += g_s2raw[(size_t)(b*8 + h)*4096 + x] * w[h];
        acc[(x>>6)*TS + (x&63)] = s;
    }
    __syncthreads();
    if (t < 64) {
        float* row = acc + t*TS;
        float mx = -3.4e38f;
        for (int j = 0; j < 64; j++) mx = fmaxf(mx, row[j]);
        float sum = 0.f;
        for (int j = 0; j < 64; j++) { float e = __expf(row[j] - mx); row[j] = e; sum += e; }
        float inv = 1.f / sum;
        float rs = 0.f;
        for (int j = 0; j < 64; j++) { float vv = row[j]*inv; row[j] = vv; rs += vv; }
        atomicMax(&g_maxcol_u, __float_as_uint(rs));
    }
    __syncthreads();
    if (t < 64) {
        float cs = 0.f;
        for (int i = 0; i < 64; i++) cs += acc[i*TS + t];
        atomicMax(&g_maxrow_u, __float_as_uint(cs));
    }
    for (int x = t; x < 4096; x += 512)
        g_attn2[(size_t)blockIdx.x*4096 + x] = acc[(x>>6)*TS + (x&63)];
}

// ---------------- K4: Moore-Penrose pinv, 256 threads ----------------
__global__ void __launch_bounds__(256) k_pinv() {
    extern __shared__ float sm[];
    float* xs = sm;
    float* zs = sm + 4224;
    float* ta = sm + 8448;
    float* tb = sm + 12672;
    int bh = blockIdx.x, t = threadIdx.x;
    int ig = t >> 4, jg = t & 15;
    for (int x = t; x < 4096; x += 256) xs[(x>>6)*TS + (x&63)] = g_attn2[(size_t)bh*4096 + x];
    __syncthreads();
    float inv = 1.f / (__uint_as_float(g_maxcol_u) * __uint_as_float(g_maxrow_u));
    for (int x = t; x < 4096; x += 256) {
        int i = x >> 6, j = x & 63;
        zs[i*TS + j] = xs[j*TS + i] * inv;
    }
    __syncthreads();
    float2 R[8], tv[8];
    for (int it = 0; it < 6; it++) {
        mmstd<64, TS>(xs, zs, R, ig, jg);
        __syncthreads();
        storeR<TS>(ta, R, ig, jg);
        __syncthreads();
        mmstd<64, TS>(ta, ta, R, ig, jg);
        #pragma unroll
        for (int r = 0; r < 4; r++) {
            tv[r*2]   = *(float2*)&ta[(ig+16*r)*TS + 2*jg];
            tv[r*2+1] = *(float2*)&ta[(ig+16*r)*TS + 2*jg + 32];
        }
        __syncthreads();
        #pragma unroll
        for (int r = 0; r < 4; r++) {
            *(float2*)&tb[(ig+16*r)*TS + 2*jg]      = make_float2(7.f*tv[r*2].x - R[r*2].x, 7.f*tv[r*2].y - R[r*2].y);
            *(float2*)&tb[(ig+16*r)*TS + 2*jg + 32] = make_float2(7.f*tv[r*2+1].x - R[r*2+1].x, 7.f*tv[r*2+1].y - R[r*2+1].y);
        }
        __syncthreads();
        mmstd<64, TS>(ta, tb, R, ig, jg);
        __syncthreads();
        #pragma unroll
        for (int r = 0; r < 4; r++) {
            *(float2*)&tb[(ig+16*r)*TS + 2*jg]      = make_float2(15.f*tv[r*2].x - R[r*2].x, 15.f*tv[r*2].y - R[r*2].y);
            *(float2*)&tb[(ig+16*r)*TS + 2*jg + 32] = make_float2(15.f*tv[r*2+1].x - R[r*2+1].x, 15.f*tv[r*2+1].y - R[r*2+1].y);
        }
        __syncthreads();
        mmstd<64, TS>(zs, tb, R, ig, jg);
        #pragma unroll
        for (int r = 0; r < 4; r++) {
            tv[r*2]   = *(float2*)&zs[(ig+16*r)*TS + 2*jg];
            tv[r*2+1] = *(float2*)&zs[(ig+16*r)*TS + 2*jg + 32];
        }
        __syncthreads();
        #pragma unroll
        for (int r = 0; r < 4; r++) {
            *(float2*)&zs[(ig+16*r)*TS + 2*jg]      = make_float2(0.25f*(13.f*tv[r*2].x - R[r*2].x), 0.25f*(13.f*tv[r*2].y - R[r*2].y));
            *(float2*)&zs[(ig+16*r)*TS + 2*jg + 32] = make_float2(0.25f*(13.f*tv[r*2+1].x - R[r*2+1].x), 0.25f*(13.f*tv[r*2+1].y - R[r*2+1].y));
        }
        __syncthreads();
    }
    for (int x = t; x < 4096; x += 256) g_zinv[(size_t)bh*4096 + x] = zs[(x>>6)*TS + (x&63)];
}

// ---------------- K5: T2 = mix(zinv, Wattn2) ----------------
__global__ void k_mixT2(const float* __restrict__ W) {
    size_t gid = (size_t)blockIdx.x*256 + threadIdx.x;
    size_t b = gid / 4096, x = gid - b*4096;
    size_t base = b*8*4096 + x;
    float a[8];
    #pragma unroll
    for (int h = 0; h < 8; h++) a[h] = g_zinv[base + (size_t)h*4096];
    #pragma unroll
    for (int kk = 0; kk < 8; kk++) {
        float s = 0.f;
        #pragma unroll
        for (int h = 0; h < 8; h++) s += a[h] * __ldg(&W[h*8 + kk]);
        g_T2[base + (size_t)kk*4096] = s;
    }
}

// ---------------- K6: sim3 (reg-staged pipeline) ----------------
__global__ void __launch_bounds__(256, 2) k_sim3(const float* __restrict__ kg, const float* __restrict__ Ws3) {
    extern __shared__ float sm[];
    float* qT  = sm;
    float* kB  = sm + 4352;
    float* raw = sm + 4352 + 2304;
    float* ws  = raw + 8*PS3;
    int b = blockIdx.x >> 7, it = blockIdx.x & 127;
    int i0 = it*32;
    int t = threadIdx.x;
    if (t < 64) ws[t] = Ws3[t];
    int ig = t >> 4, jg = t & 15;
    float rq[16], rk[8];
    {
        const float* qsrc = g_ql + (size_t)(b*8)*4096;
        const float* ksrc = kg + ((size_t)(b*8)*NN + i0)*DD;
        #pragma unroll
        for (int s = 0; s < 16; s++) rq[s] = qsrc[t + 256*s];
        #pragma unroll
        for (int s = 0; s < 8; s++) rk[s] = ksrc[t + 256*s];
    }
    for (int h = 0; h < 8; h++) {
        __syncthreads();
        #pragma unroll
        for (int s = 0; s < 16; s++) { int x = t + 256*s; qT[(x&63)*ATS + (x>>6)] = rq[s]; }
        #pragma unroll
        for (int s = 0; s < 8; s++)  { int x = t + 256*s; kB[(x&63)*ITS + (x>>6)] = rk[s]; }
        __syncthreads();
        if (h < 7) {
            const float* qsrc = g_ql + (size_t)(b*8 + h + 1)*4096;
            const float* ksrc = kg + ((size_t)(b*8 + h + 1)*NN + i0)*DD;
            #pragma unroll
            for (int s = 0; s < 16; s++) rq[s] = qsrc[t + 256*s];
            #pragma unroll
            for (int s = 0; s < 8; s++) rk[s] = ksrc[t + 256*s];
        }
        float2 R[4];
        #pragma unroll
        for (int u = 0; u < 4; u++) R[u] = make_float2(0.f, 0.f);
        #pragma unroll 4
        for (int k = 0; k < 64; k++) {
            float4 a = *(const float4*)&qT[k*ATS + 4*ig];
            float2 bb = *(const float2*)&kB[k*ITS + 2*jg];
            ffma2(R[0], a.x, bb); ffma2(R[1], a.y, bb);
            ffma2(R[2], a.z, bb); ffma2(R[3], a.w, bb);
        }
        #pragma unroll
        for (int r = 0; r < 4; r++)
            *(float2*)&raw[h*PS3 + (4*ig + r)*ITS + 2*jg] = R[r];
    }
    __syncthreads();
    for (int x = t; x < 1024; x += 256) mix8v<PS3>(raw, ws, (x>>4)*ITS + 2*(x&15));
    __syncthreads();
    for (int x = t; x < 8192; x += 256) {
        int i2 = x & 15, j = (x >> 4) & 63, kk = x >> 10;
        *(float2*)&g_G3a[((size_t)(b*8 + kk)*64 + j)*NN + i0 + 2*i2] =
            *(const float2*)&raw[kk*PS3 + j*ITS + 2*i2];
    }
}

// ---------------- K7: per-row max & 1/sum of exp ----------------
__global__ void k_rowstat() {
    __shared__ float red[256];
    size_t base = (size_t)blockIdx.x * NN;
    int t = threadIdx.x;
    float v[16], mx = -3.4e38f;
    #pragma unroll
    for (int s = 0; s < 16; s++) { v[s] = g_G3a[base + t + 256*s]; mx = fmaxf(mx, v[s]); }
    red[t] = mx; __syncthreads();
    for (int o = 128; o > 0; o >>= 1) { if (t < o) red[t] = fmaxf(red[t], red[t+o]); __syncthreads(); }
    mx = red[0]; __syncthreads();
    float sum = 0.f;
    #pragma unroll
    for (int s = 0; s < 16; s++) sum += __expf(v[s] - mx);
    red[t] = sum; __syncthreads();
    for (int o = 128; o > 0; o >>= 1) { if (t < o) red[t] += red[t+o]; __syncthreads(); }
    if (t == 0) { g_stats[blockIdx.x*2] = mx; g_stats[blockIdx.x*2 + 1] = 1.f/red[0]; }
}

// ---------------- K8: fused exp-normalize + Wattn3 mix -> g_G3b ----------------
__global__ void __launch_bounds__(256) k_a3norm(const float* __restrict__ Wa3) {
    int b = blockIdx.y;
    int x = blockIdx.x*256 + threadIdx.x;
    int j = x >> 11, i2 = x & 2047;
    float2 e[8];
    #pragma unroll
    for (int kk = 0; kk < 8; kk++) {
        size_t row = (size_t)(b*8 + kk)*64 + j;
        float2 v = *(const float2*)&g_G3a[row*NN + 2*i2];
        float mx = g_stats[row*2], inv = g_stats[row*2 + 1];
        e[kk] = make_float2(__expf(v.x - mx)*inv, __expf(v.y - mx)*inv);
    }
    #pragma unroll
    for (int k2 = 0; k2 < 8; k2++) {
        float2 s = make_float2(0.f, 0.f);
        #pragma unroll
        for (int kk = 0; kk < 8; kk++) ffma2(s, __ldg(&Wa3[kk*8 + k2]), e[kk]);
        *(float2*)&g_G3b[((size_t)(b*8 + k2)*64 + j)*NN + 2*i2] = s;
    }
}

// ---------------- K9: split-K partials (128-row tiles, 2 CTA/SM) ----------------
__global__ void __launch_bounds__(256, 2) k_spart(const float* __restrict__ vg) {
    extern __shared__ float sm[];
    float* At = sm;            // 128*ATS [i][j]
    float* vt = sm + 128*ATS;  // 128*TS  [i][d]
    int bk = blockIdx.x, p = blockIdx.y;
    int t = threadIdx.x;
    const float* asrc = g_G3b + (size_t)bk*64*NN + p*128;
    for (int x = t; x < 8192; x += 256) {
        int j = x >> 7, i = x & 127;
        At[i*ATS + j] = asrc[(size_t)j*NN + i];
    }
    const float* vsrc = vg + ((size_t)bk*NN + p*128)*DD;
    for (int x = t; x < 8192; x += 256) vt[(x>>6)*TS + (x&63)] = vsrc[x];
    __syncthreads();
    int ig = t >> 4, jg = t & 15;
    float2 R[8];
    mmstd4<128, ATS>(At, vt, R, ig, jg);
    storeR4<64>(g_Sp + ((size_t)bk*NP + p)*4096, R, ig, jg);
}

// ---------------- K10: reduce 32 partials; M = T2 @ S ----------------
__global__ void __launch_bounds__(256) k_mfin() {
    __shared__ float t2T[64*ATS];
    __shared__ float ss[64*TS];
    int bk = blockIdx.x, t = threadIdx.x;
    for (int x = t; x < 4096; x += 256) {
        int r = x >> 6, c = x & 63;
        float s = 0.f;
        #pragma unroll
        for (int p = 0; p < NP; p++) s += g_Sp[((size_t)bk*NP + p)*4096 + x];
        ss[r*TS + c] = s;
        t2T[c*ATS + r] = g_T2[(size_t)bk*4096 + x];
    }
    __syncthreads();
    int ig = t >> 4, jg = t & 15;
    float2 R[8];
    mmstd4<64, ATS>(t2T, ss, R, ig, jg);
    storeR4<64>(g_M + (size_t)bk*4096, R, ig, jg);
}

// ---------------- K11: fused sim1 path (transposed planes, FMA-bound tiles) ----------------
__global__ void __launch_bounds__(256, 2) k_sim1out(const float* __restrict__ qg,
                          const float* __restrict__ Ws1,
                          const float* __restrict__ Wa1,
                          float* __restrict__ out) {
    extern __shared__ float sm[];
    float* qT  = sm;                  // 64*ITS [d][i]
    float* kB  = sm + 2304;           // 64*TS [d][j], later M [j][d]
    float* raw = sm + 2304 + 4224;    // 8*PS1T transposed planes [j][i], row stride ITS
    float* wsa = raw + 8*PS1T;
    float* wsb = wsa + 64;
    int b = blockIdx.x >> 7, it = blockIdx.x & 127;
    int i0 = it*32;
    int t = threadIdx.x;
    if (t < 64) { wsa[t] = Ws1[t]; wsb[t] = Wa1[t]; }
    int ig = (t >> 4) & 7;   // i rows 4ig..4ig+3 (warp-uniformish -> broadcast A reads)
    int jg = t & 15;         // j/d col pairs 2jg, 2jg+32
    {   // main loop: C[i][j] = q·kl, register-staged prefetch, stored transposed [j][i]
        float rk[16], rq[8];
        {
            const float* ksrc = g_kl + (size_t)(b*8)*4096;
            const float* qsrc = qg + ((size_t)(b*8)*NN + i0)*DD;
            #pragma unroll
            for (int s = 0; s < 16; s++) rk[s] = ksrc[t + 256*s];
            #pragma unroll
            for (int s = 0; s < 8; s++) rq[s] = qsrc[t + 256*s];
        }
        for (int h = 0; h < 8; h++) {
            __syncthreads();
            #pragma unroll
            for (int s = 0; s < 16; s++) { int x = t + 256*s; kB[(x&63)*TS + (x>>6)] = rk[s]; }
            #pragma unroll
            for (int s = 0; s < 8; s++)  { int x = t + 256*s; qT[(x&63)*ITS + (x>>6)] = rq[s]; }
            __syncthreads();
            if (h < 7) {
                const float* ksrc = g_kl + (size_t)(b*8 + h + 1)*4096;
                const float* qsrc = qg + ((size_t)(b*8 + h + 1)*NN + i0)*DD;
                #pragma unroll
                for (int s = 0; s < 16; s++) rk[s] = ksrc[t + 256*s];
                #pragma unroll
                for (int s = 0; s < 8; s++) rq[s] = qsrc[t + 256*s];
            }
            float2 R[8];
            #pragma unroll
            for (int u = 0; u < 8; u++) R[u] = make_float2(0.f, 0.f);
            #pragma unroll 4
            for (int d = 0; d < 64; d++) {
                float4 a  = *(const float4*)&qT[d*ITS + 4*ig];
                float2 b0 = *(const float2*)&kB[d*TS + 2*jg];
                float2 b1 = *(const float2*)&kB[d*TS + 2*jg + 32];
                ffma2(R[0], a.x, b0); ffma2(R[1], a.y, b0);
                ffma2(R[2], a.z, b0); ffma2(R[3], a.w, b0);
                ffma2(R[4], a.x, b1); ffma2(R[5], a.y, b1);
                ffma2(R[6], a.z, b1); ffma2(R[7], a.w, b1);
            }
            // R[r] = C[4ig+r][2jg..2jg+1], R[4+r] = C[4ig+r][2jg+32..33]
            float* pl = raw + h*PS1T;
            *(float4*)&pl[(2*jg     )*ITS + 4*ig] = make_float4(R[0].x, R[1].x, R[2].x, R[3].x);
            *(float4*)&pl[(2*jg + 1 )*ITS + 4*ig] = make_float4(R[0].y, R[1].y, R[2].y, R[3].y);
            *(float4*)&pl[(2*jg + 32)*ITS + 4*ig] = make_float4(R[4].x, R[5].x, R[6].x, R[7].x);
            *(float4*)&pl[(2*jg + 33)*ITS + 4*ig] = make_float4(R[4].y, R[5].y, R[6].y, R[7].y);
        }
    }
    __syncthreads();
    for (int x = t; x < 1024; x += 256) mix8v<PS1T>(raw, wsa, (x>>4)*ITS + 2*(x&15));
    __syncthreads();
    {   // softmax over j (plane rows) for each (kk, i): column walk
        int kk = t >> 5, i = t & 31;
        float* col = raw + kk*PS1T + i;
        float mx = -3.4e38f;
        for (int j = 0; j < 64; j++) mx = fmaxf(mx, col[j*ITS]);
        float sum = 0.f;
        for (int j = 0; j < 64; j++) { float e = __expf(col[j*ITS] - mx); col[j*ITS] = e; sum += e; }
        float inv = 1.f / sum;
        for (int j = 0; j < 64; j++) col[j*ITS] *= inv;
    }
    __syncthreads();
    for (int x = t; x < 1024; x += 256) mix8v<PS1T>(raw, wsb, (x>>4)*ITS + 2*(x&15));
    {   // epilogue: out[i][d] = sum_j P[j][i] M[j][d], M-plane prefetch
        float rm[16];
        {
            const float* msrc = g_M + (size_t)(b*8)*4096;
            #pragma unroll
            for (int s = 0; s < 16; s++) rm[s] = msrc[t + 256*s];
        }
        for (int kk = 0; kk < 8; kk++) {
            __syncthreads();
            #pragma unroll
            for (int s = 0; s < 16; s++) { int x = t + 256*s; kB[(x>>6)*TS + (x&63)] = rm[s]; }
            __syncthreads();
            if (kk < 7) {
                const float* msrc = g_M + (size_t)(b*8 + kk + 1)*4096;
                #pragma unroll
                for (int s = 0; s < 16; s++) rm[s] = msrc[t + 256*s];
            }
            const float* pl = raw + kk*PS1T;
            float2 R[8];
            #pragma unroll
            for (int u = 0; u < 8; u++) R[u] = make_float2(0.f, 0.f);
            #pragma unroll 4
            for (int j = 0; j < 64; j++) {
                float4 a  = *(const float4*)&pl[j*ITS + 4*ig];
                float2 b0 = *(const float2*)&kB[j*TS + 2*jg];
                float2 b1 = *(const float2*)&kB[j*TS + 2*jg + 32];
                ffma2(R[0], a.x, b0); ffma2(R[1], a.y, b0);
                ffma2(R[2], a.z, b0); ffma2(R[3], a.w, b0);
                ffma2(R[4], a.x, b1); ffma2(R[5], a.y, b1);
                ffma2(R[6], a.z, b1); ffma2(R[7], a.w, b1);
            }
            size_t ob = ((size_t)(b*8 + kk)*NN + i0)*DD;
            #pragma unroll
            for (int r = 0; r < 4; r++) {
                *(float2*)&out[ob + (size_t)(4*ig + r)*DD + 2*jg]      = R[r];
                *(float2*)&out[ob + (size_t)(4*ig + r)*DD + 2*jg + 32] = R[4 + r];
            }
        }
    }
}

// ---------------- K12: residual conv (8-row tiles, 2 CTA/SM, RMW on out) ----------------
__device__ __forceinline__ void ffma2v(float2& a, const float2 b, const float2 c) {
    asm("fma.rn.f32x2 %0, %1, %2, %0;"
        : "+l"(reinterpret_cast<unsigned long long&>(a))
        : "l"(reinterpret_cast<const unsigned long long&>(b)),
          "l"(reinterpret_cast<const unsigned long long&>(c)));
}
__global__ void __launch_bounds__(256, 2) k_conv(const float* __restrict__ vg,
                                                 const float* __restrict__ cw,
                                                 float* __restrict__ out) {
    extern __shared__ float sm[];
    float2* vv2 = (float2*)sm;      // 8h * 40n * 32dp float2
    float* ws = sm + 20480;
    int b = blockIdx.x >> 9, nt = blockIdx.x & 511;
    int n0 = nt*8;
    int t = threadIdx.x;
    const float2* vg2 = (const float2*)vg;
    for (int x = t; x < 10240; x += 256) {
        int h = x / 1280, rem = x - h*1280;
        int i = rem >> 5, dp = rem & 31;
        int na = n0 - 16 + i;
        float2 val = make_float2(0.f, 0.f);
        if (na >= 0 && na < NN) val = vg2[((size_t)(b*8 + h)*NN + na)*32 + dp];
        vv2[h*1280 + i*32 + dp] = val;
    }
    for (int x = t; x < 2112; x += 256) ws[x] = cw[x];
    __syncthreads();
    int k = t >> 5, dp = t & 31;
    float2 acc[8];
    #pragma unroll
    for (int n = 0; n < 8; n++) acc[n] = make_float2(0.f, 0.f);
    float2 vr[40];
    for (int h = 0; h < 8; h++) {
        #pragma unroll
        for (int i = 0; i < 40; i++) vr[i] = vv2[h*1280 + i*32 + dp];
        const float* wrow = ws + k*264 + h*33;
        #pragma unroll
        for (int tt = 0; tt < 33; tt++) {
            float2 w2 = make_float2(wrow[tt], wrow[tt]);
            #pragma unroll
            for (int n = 0; n < 8; n++) ffma2v(acc[n], w2, vr[n + tt]);
        }
    }
    float2* op = (float2*)out + ((size_t)(b*8 + k)*NN + n0)*32 + dp;
    #pragma unroll
    for (int n = 0; n < 8; n++) {
        float2 cur = op[(size_t)n*32];
        cur.x += acc[n].x; cur.y += acc[n].y;
        op[(size_t)n*32] = cur;
    }
}

// ---------------- launch ----------------
extern "C" void kernel_launch(void* const* d_in, const int* in_sizes, int n_in,
                              void* d_out, int out_size) {
    const float* q   = (const float*)d_in[0];
    const float* k   = (const float*)d_in[1];
    const float* v   = (const float*)d_in[2];
    const float* Ws1 = (const float*)d_in[3];
    const float* Ws2 = (const float*)d_in[4];
    const float* Ws3 = (const float*)d_in[5];
    const float* Wa1 = (const float*)d_in[6];
    const float* Wa2 = (const float*)d_in[7];
    const float* Wa3 = (const float*)d_in[8];
    const float* cw  = (const float*)d_in[9];
    float* out = (float*)d_out;

    const int SMEM_PINV = 16896*4;
    const int SMEM_SIM3 = (4352 + 2304 + 8*PS3 + 64)*4;
    const int SMEM_SIM1 = (2304 + 4224 + 8*PS1T + 128)*4;   // 100480
    const int SMEM_SPART = (128*ATS + 128*TS)*4;
    const int SMEM_CONV = (20480 + 2112)*4;
    cudaFuncSetAttribute(k_pinv,   cudaFuncAttributeMaxDynamicSharedMemorySize, SMEM_PINV);
    cudaFuncSetAttribute(k_sim3,   cudaFuncAttributeMaxDynamicSharedMemorySize, SMEM_SIM3);
    cudaFuncSetAttribute(k_spart,  cudaFuncAttributeMaxDynamicSharedMemorySize, SMEM_SPART);
    cudaFuncSetAttribute(k_sim1out,cudaFuncAttributeMaxDynamicSharedMemorySize, SMEM_SIM1);
    cudaFuncSetAttribute(k_conv,   cudaFuncAttributeMaxDynamicSharedMemorySize, SMEM_CONV);

    k_landmarks<<<dim3(64, 16), 256>>>(q, k);
    k_sim2dots<<<64, 512>>>();
    k_sim2mix<<<64, 512>>>(Ws2);
    k_pinv<<<64, 256, SMEM_PINV>>>();
    k_mixT2<<<128, 256>>>(Wa2);
    k_sim3<<<1024, 256, SMEM_SIM3>>>(k, Ws3);
    k_rowstat<<<4096, 256>>>();
    k_a3norm<<<dim3(512, 8), 256>>>(Wa3);
    k_spart<<<dim3(64, 32), 256, SMEM_SPART>>>(v);
    k_mfin<<<64, 256>>>();
    k_sim1out<<<1024, 256, SMEM_SIM1>>>(q, Ws1, Wa1, out);
    k_conv<<<4096, 256, SMEM_CONV>>>(v, cw, out);
}

// round 15
// speedup vs baseline: 1.0615x; 1.0615x over previous
#include <cuda_runtime.h>

#define BB 8
#define HH 8
#define NN 4096
#define DD 64
#define MM 64
#define TS 66          // 64-wide row stride (float2 aligned)
#define ATS 68         // transposed-A stride, float4 aligned
#define ITS 36         // 32-wide row stride, float4 aligned
#define PS3 2312       // sim3 plane: 64*36+8
#define PS1 2116       // sim1 plane: 32*66+4
#define NP 32          // spart partials per (b,k)

// ---------------- scratch ----------------
__device__ float g_ql[BB*HH*MM*DD];
__device__ float g_kl[BB*HH*MM*DD];
__device__ float g_s2raw[BB*HH*MM*MM];
__device__ float g_attn2[BB*HH*MM*MM];
__device__ float g_zinv[BB*HH*MM*MM];
__device__ float g_T2[BB*HH*MM*MM];
__device__ float g_Sp[(size_t)BB*HH*NP*MM*DD];
__device__ float g_M[BB*HH*MM*DD];
__device__ float g_G3a[(size_t)BB*HH*MM*NN];
__device__ float g_G3b[(size_t)BB*HH*MM*NN];
__device__ float g_stats[BB*HH*MM*2];
__device__ unsigned int g_maxcol_u, g_maxrow_u;

__device__ __forceinline__ void ffma2(float2& a, float b, const float2 c) {
    float2 bb = make_float2(b, b);
    asm("fma.rn.f32x2 %0, %1, %2, %0;"
        : "+l"(reinterpret_cast<unsigned long long&>(a))
        : "l"(reinterpret_cast<const unsigned long long&>(bb)),
          "l"(reinterpret_cast<const unsigned long long&>(c)));
}

template<int L, int AS>
__device__ __forceinline__ void mmstd(const float* __restrict__ A, const float* __restrict__ B,
                                      float2 R[8], int ig, int jg) {
    #pragma unroll
    for (int u = 0; u < 8; u++) R[u] = make_float2(0.f, 0.f);
    #pragma unroll 4
    for (int k = 0; k < L; k++) {
        float a0 = A[(ig     )*AS + k];
        float a1 = A[(ig + 16)*AS + k];
        float a2 = A[(ig + 32)*AS + k];
        float a3 = A[(ig + 48)*AS + k];
        float2 b0 = *(const float2*)&B[k*TS + 2*jg];
        float2 b1 = *(const float2*)&B[k*TS + 2*jg + 32];
        ffma2(R[0], a0, b0); ffma2(R[1], a0, b1);
        ffma2(R[2], a1, b0); ffma2(R[3], a1, b1);
        ffma2(R[4], a2, b0); ffma2(R[5], a2, b1);
        ffma2(R[6], a3, b0); ffma2(R[7], a3, b1);
    }
}
template<int L, int AS>
__device__ __forceinline__ void mmstd4(const float* __restrict__ At, const float* __restrict__ B,
                                       float2 R[8], int ig, int jg) {
    #pragma unroll
    for (int u = 0; u < 8; u++) R[u] = make_float2(0.f, 0.f);
    #pragma unroll 4
    for (int k = 0; k < L; k++) {
        float4 a = *(const float4*)&At[k*AS + 4*ig];
        float2 b0 = *(const float2*)&B[k*TS + 2*jg];
        float2 b1 = *(const float2*)&B[k*TS + 2*jg + 32];
        ffma2(R[0], a.x, b0); ffma2(R[1], a.x, b1);
        ffma2(R[2], a.y, b0); ffma2(R[3], a.y, b1);
        ffma2(R[4], a.z, b0); ffma2(R[5], a.z, b1);
        ffma2(R[6], a.w, b0); ffma2(R[7], a.w, b1);
    }
}
template<int S>
__device__ __forceinline__ void storeR(float* __restrict__ dst, const float2 R[8], int ig, int jg) {
    #pragma unroll
    for (int r = 0; r < 4; r++) {
        *(float2*)&dst[(size_t)(ig + 16*r)*S + 2*jg]      = R[2*r];
        *(float2*)&dst[(size_t)(ig + 16*r)*S + 2*jg + 32] = R[2*r + 1];
    }
}
template<int S>
__device__ __forceinline__ void storeR4(float* __restrict__ dst, const float2 R[8], int ig, int jg) {
    #pragma unroll
    for (int r = 0; r < 4; r++) {
        *(float2*)&dst[(size_t)(4*ig + r)*S + 2*jg]      = R[2*r];
        *(float2*)&dst[(size_t)(4*ig + r)*S + 2*jg + 32] = R[2*r + 1];
    }
}
template<int PSv>
__device__ __forceinline__ void mix8v(float* __restrict__ raw, const float* __restrict__ ws, int p) {
    float2 a[8];
    #pragma unroll
    for (int h = 0; h < 8; h++) a[h] = *(const float2*)&raw[h*PSv + p];
    #pragma unroll
    for (int kk = 0; kk < 8; kk++) {
        float2 s = make_float2(0.f, 0.f);
        #pragma unroll
        for (int h = 0; h < 8; h++) ffma2(s, ws[h*8 + kk], a[h]);
        *(float2*)&raw[kk*PSv + p] = s;
    }
}

// ---------------- K1: landmarks (+ atomic reset) ----------------
__global__ void __launch_bounds__(256) k_landmarks(const float* __restrict__ q, const float* __restrict__ k) {
    if (blockIdx.x == 0 && blockIdx.y == 0 && threadIdx.x == 0) {
        g_maxcol_u = 0u; g_maxrow_u = 0u;
    }
    int bh = blockIdx.x;
    int mi = blockIdx.y*4 + (threadIdx.x >> 6);
    int d  = threadIdx.x & 63;
    const float* qp = q + ((size_t)bh*NN + (size_t)mi*64)*DD + d;
    const float* kp = k + ((size_t)bh*NN + (size_t)mi*64)*DD + d;
    float sq = 0.f, sk = 0.f;
    #pragma unroll 8
    for (int t = 0; t < 64; t++) { sq += qp[(size_t)t*DD]; sk += kp[(size_t)t*DD]; }
    g_ql[(bh*MM + mi)*DD + d] = sq * (1.f/64.f);
    g_kl[(bh*MM + mi)*DD + d] = sk * (1.f/64.f);
}

// ---------------- K2a: sim2 raw dots, 512 threads ----------------
__global__ void __launch_bounds__(512) k_sim2dots() {
    __shared__ float qa[64*TS];
    __shared__ float kb[64*TS];
    int bh = blockIdx.x, t = threadIdx.x;
    const float* qsrc = g_ql + (size_t)bh*4096;
    const float* ksrc = g_kl + (size_t)bh*4096;
    for (int x = t; x < 4096; x += 512) {
        int i = x >> 6, d = x & 63;
        qa[i*TS + d] = qsrc[x];
        kb[d*TS + i] = ksrc[x];
    }
    __syncthreads();
    int ig = t >> 4, jg = t & 15;
    float2 R[4];
    #pragma unroll
    for (int u = 0; u < 4; u++) R[u] = make_float2(0.f, 0.f);
    #pragma unroll 4
    for (int k = 0; k < 64; k++) {
        float a0 = qa[(ig     )*TS + k];
        float a1 = qa[(ig + 32)*TS + k];
        float2 b0 = *(const float2*)&kb[k*TS + 2*jg];
        float2 b1 = *(const float2*)&kb[k*TS + 2*jg + 32];
        ffma2(R[0], a0, b0); ffma2(R[1], a0, b1);
        ffma2(R[2], a1, b0); ffma2(R[3], a1, b1);
    }
    float* dst = g_s2raw + (size_t)bh*4096;
    *(float2*)&dst[(ig     )*64 + 2*jg]      = R[0];
    *(float2*)&dst[(ig     )*64 + 2*jg + 32] = R[1];
    *(float2*)&dst[(ig + 32)*64 + 2*jg]      = R[2];
    *(float2*)&dst[(ig + 32)*64 + 2*jg + 32] = R[3];
}

// ---------------- K2b: mix + softmax + scale sums -> attn2, 512 threads ----------------
__global__ void __launch_bounds__(512) k_sim2mix(const float* __restrict__ W) {
    __shared__ float acc[64*TS];
    int b = blockIdx.x >> 3, kk = blockIdx.x & 7;
    int t = threadIdx.x;
    float w[8];
    #pragma unroll
    for (int h = 0; h < 8; h++) w[h] = __ldg(&W[h*8 + kk]);
    for (int x = t; x < 4096; x += 512) {
        float s = 0.f;
        #pragma unroll
        for (int h = 0; h < 8; h++) s += g_s2raw[(size_t)(b*8 + h)*4096 + x] * w[h];
        acc[(x>>6)*TS + (x&63)] = s;
    }
    __syncthreads();
    if (t < 64) {
        float* row = acc + t*TS;
        float mx = -3.4e38f;
        for (int j = 0; j < 64; j++) mx = fmaxf(mx, row[j]);
        float sum = 0.f;
        for (int j = 0; j < 64; j++) { float e = __expf(row[j] - mx); row[j] = e; sum += e; }
        float inv = 1.f / sum;
        float rs = 0.f;
        for (int j = 0; j < 64; j++) { float vv = row[j]*inv; row[j] = vv; rs += vv; }
        atomicMax(&g_maxcol_u, __float_as_uint(rs));
    }
    __syncthreads();
    if (t < 64) {
        float cs = 0.f;
        for (int i = 0; i < 64; i++) cs += acc[i*TS + t];
        atomicMax(&g_maxrow_u, __float_as_uint(cs));
    }
    for (int x = t; x < 4096; x += 512)
        g_attn2[(size_t)blockIdx.x*4096 + x] = acc[(x>>6)*TS + (x&63)];
}

// ---------------- K4: Moore-Penrose pinv, 256 threads ----------------
__global__ void __launch_bounds__(256) k_pinv() {
    extern __shared__ float sm[];
    float* xs = sm;
    float* zs = sm + 4224;
    float* ta = sm + 8448;
    float* tb = sm + 12672;
    int bh = blockIdx.x, t = threadIdx.x;
    int ig = t >> 4, jg = t & 15;
    for (int x = t; x < 4096; x += 256) xs[(x>>6)*TS + (x&63)] = g_attn2[(size_t)bh*4096 + x];
    __syncthreads();
    float inv = 1.f / (__uint_as_float(g_maxcol_u) * __uint_as_float(g_maxrow_u));
    for (int x = t; x < 4096; x += 256) {
        int i = x >> 6, j = x & 63;
        zs[i*TS + j] = xs[j*TS + i] * inv;
    }
    __syncthreads();
    float2 R[8], tv[8];
    for (int it = 0; it < 6; it++) {
        mmstd<64, TS>(xs, zs, R, ig, jg);
        __syncthreads();
        storeR<TS>(ta, R, ig, jg);
        __syncthreads();
        mmstd<64, TS>(ta, ta, R, ig, jg);
        #pragma unroll
        for (int r = 0; r < 4; r++) {
            tv[r*2]   = *(float2*)&ta[(ig+16*r)*TS + 2*jg];
            tv[r*2+1] = *(float2*)&ta[(ig+16*r)*TS + 2*jg + 32];
        }
        __syncthreads();
        #pragma unroll
        for (int r = 0; r < 4; r++) {
            *(float2*)&tb[(ig+16*r)*TS + 2*jg]      = make_float2(7.f*tv[r*2].x - R[r*2].x, 7.f*tv[r*2].y - R[r*2].y);
            *(float2*)&tb[(ig+16*r)*TS + 2*jg + 32] = make_float2(7.f*tv[r*2+1].x - R[r*2+1].x, 7.f*tv[r*2+1].y - R[r*2+1].y);
        }
        __syncthreads();
        mmstd<64, TS>(ta, tb, R, ig, jg);
        __syncthreads();
        #pragma unroll
        for (int r = 0; r < 4; r++) {
            *(float2*)&tb[(ig+16*r)*TS + 2*jg]      = make_float2(15.f*tv[r*2].x - R[r*2].x, 15.f*tv[r*2].y - R[r*2].y);
            *(float2*)&tb[(ig+16*r)*TS + 2*jg + 32] = make_float2(15.f*tv[r*2+1].x - R[r*2+1].x, 15.f*tv[r*2+1].y - R[r*2+1].y);
        }
        __syncthreads();
        mmstd<64, TS>(zs, tb, R, ig, jg);
        #pragma unroll
        for (int r = 0; r < 4; r++) {
            tv[r*2]   = *(float2*)&zs[(ig+16*r)*TS + 2*jg];
            tv[r*2+1] = *(float2*)&zs[(ig+16*r)*TS + 2*jg + 32];
        }
        __syncthreads();
        #pragma unroll
        for (int r = 0; r < 4; r++) {
            *(float2*)&zs[(ig+16*r)*TS + 2*jg]      = make_float2(0.25f*(13.f*tv[r*2].x - R[r*2].x), 0.25f*(13.f*tv[r*2].y - R[r*2].y));
            *(float2*)&zs[(ig+16*r)*TS + 2*jg + 32] = make_float2(0.25f*(13.f*tv[r*2+1].x - R[r*2+1].x), 0.25f*(13.f*tv[r*2+1].y - R[r*2+1].y));
        }
        __syncthreads();
    }
    for (int x = t; x < 4096; x += 256) g_zinv[(size_t)bh*4096 + x] = zs[(x>>6)*TS + (x&63)];
}

// ---------------- K5: T2 = mix(zinv, Wattn2) ----------------
__global__ void k_mixT2(const float* __restrict__ W) {
    size_t gid = (size_t)blockIdx.x*256 + threadIdx.x;
    size_t b = gid / 4096, x = gid - b*4096;
    size_t base = b*8*4096 + x;
    float a[8];
    #pragma unroll
    for (int h = 0; h < 8; h++) a[h] = g_zinv[base + (size_t)h*4096];
    #pragma unroll
    for (int kk = 0; kk < 8; kk++) {
        float s = 0.f;
        #pragma unroll
        for (int h = 0; h < 8; h++) s += a[h] * __ldg(&W[h*8 + kk]);
        g_T2[base + (size_t)kk*4096] = s;
    }
}

// ---------------- K6: sim3 (reg-staged pipeline) ----------------
__global__ void __launch_bounds__(256, 2) k_sim3(const float* __restrict__ kg, const float* __restrict__ Ws3) {
    extern __shared__ float sm[];
    float* qT  = sm;
    float* kB  = sm + 4352;
    float* raw = sm + 4352 + 2304;
    float* ws  = raw + 8*PS3;
    int b = blockIdx.x >> 7, it = blockIdx.x & 127;
    int i0 = it*32;
    int t = threadIdx.x;
    if (t < 64) ws[t] = Ws3[t];
    int ig = t >> 4, jg = t & 15;
    float rq[16], rk[8];
    {
        const float* qsrc = g_ql + (size_t)(b*8)*4096;
        const float* ksrc = kg + ((size_t)(b*8)*NN + i0)*DD;
        #pragma unroll
        for (int s = 0; s < 16; s++) rq[s] = qsrc[t + 256*s];
        #pragma unroll
        for (int s = 0; s < 8; s++) rk[s] = ksrc[t + 256*s];
    }
    for (int h = 0; h < 8; h++) {
        __syncthreads();
        #pragma unroll
        for (int s = 0; s < 16; s++) { int x = t + 256*s; qT[(x&63)*ATS + (x>>6)] = rq[s]; }
        #pragma unroll
        for (int s = 0; s < 8; s++)  { int x = t + 256*s; kB[(x&63)*ITS + (x>>6)] = rk[s]; }
        __syncthreads();
        if (h < 7) {
            const float* qsrc = g_ql + (size_t)(b*8 + h + 1)*4096;
            const float* ksrc = kg + ((size_t)(b*8 + h + 1)*NN + i0)*DD;
            #pragma unroll
            for (int s = 0; s < 16; s++) rq[s] = qsrc[t + 256*s];
            #pragma unroll
            for (int s = 0; s < 8; s++) rk[s] = ksrc[t + 256*s];
        }
        float2 R[4];
        #pragma unroll
        for (int u = 0; u < 4; u++) R[u] = make_float2(0.f, 0.f);
        #pragma unroll 4
        for (int k = 0; k < 64; k++) {
            float4 a = *(const float4*)&qT[k*ATS + 4*ig];
            float2 bb = *(const float2*)&kB[k*ITS + 2*jg];
            ffma2(R[0], a.x, bb); ffma2(R[1], a.y, bb);
            ffma2(R[2], a.z, bb); ffma2(R[3], a.w, bb);
        }
        #pragma unroll
        for (int r = 0; r < 4; r++)
            *(float2*)&raw[h*PS3 + (4*ig + r)*ITS + 2*jg] = R[r];
    }
    __syncthreads();
    for (int x = t; x < 1024; x += 256) mix8v<PS3>(raw, ws, (x>>4)*ITS + 2*(x&15));
    __syncthreads();
    for (int x = t; x < 8192; x += 256) {
        int i2 = x & 15, j = (x >> 4) & 63, kk = x >> 10;
        *(float2*)&g_G3a[((size_t)(b*8 + kk)*64 + j)*NN + i0 + 2*i2] =
            *(const float2*)&raw[kk*PS3 + j*ITS + 2*i2];
    }
}

// ---------------- K7: per-row max & 1/sum of exp (float4 loads) ----------------
__global__ void k_rowstat() {
    __shared__ float red[256];
    const float4* row = (const float4*)(g_G3a + (size_t)blockIdx.x * NN);
    int t = threadIdx.x;
    float4 v[4];
    float mx = -3.4e38f;
    #pragma unroll
    for (int s = 0; s < 4; s++) {
        v[s] = row[t + 256*s];
        mx = fmaxf(mx, fmaxf(fmaxf(v[s].x, v[s].y), fmaxf(v[s].z, v[s].w)));
    }
    red[t] = mx; __syncthreads();
    for (int o = 128; o > 0; o >>= 1) { if (t < o) red[t] = fmaxf(red[t], red[t+o]); __syncthreads(); }
    mx = red[0]; __syncthreads();
    float sum = 0.f;
    #pragma unroll
    for (int s = 0; s < 4; s++)
        sum += __expf(v[s].x - mx) + __expf(v[s].y - mx) + __expf(v[s].z - mx) + __expf(v[s].w - mx);
    red[t] = sum; __syncthreads();
    for (int o = 128; o > 0; o >>= 1) { if (t < o) red[t] += red[t+o]; __syncthreads(); }
    if (t == 0) { g_stats[blockIdx.x*2] = mx; g_stats[blockIdx.x*2 + 1] = 1.f/red[0]; }
}

// ---------------- K8: fused exp-normalize + Wattn3 mix -> g_G3b (float4) ----------------
__global__ void __launch_bounds__(256) k_a3norm(const float* __restrict__ Wa3) {
    int b = blockIdx.y;
    int x = blockIdx.x*256 + threadIdx.x;   // float4 index within batch: 0..65535
    int j = x >> 10, i4 = x & 1023;
    float4 e[8];
    #pragma unroll
    for (int kk = 0; kk < 8; kk++) {
        size_t row = (size_t)(b*8 + kk)*64 + j;
        float4 v = *(const float4*)&g_G3a[row*NN + 4*i4];
        float mx = g_stats[row*2], inv = g_stats[row*2 + 1];
        e[kk] = make_float4(__expf(v.x - mx)*inv, __expf(v.y - mx)*inv,
                            __expf(v.z - mx)*inv, __expf(v.w - mx)*inv);
    }
    #pragma unroll
    for (int k2 = 0; k2 < 8; k2++) {
        float2 s0 = make_float2(0.f, 0.f), s1 = make_float2(0.f, 0.f);
        #pragma unroll
        for (int kk = 0; kk < 8; kk++) {
            float w = __ldg(&Wa3[kk*8 + k2]);
            ffma2(s0, w, make_float2(e[kk].x, e[kk].y));
            ffma2(s1, w, make_float2(e[kk].z, e[kk].w));
        }
        *(float4*)&g_G3b[((size_t)(b*8 + k2)*64 + j)*NN + 4*i4] = make_float4(s0.x, s0.y, s1.x, s1.y);
    }
}

// ---------------- K9: split-K partials (128-row tiles, 2 CTA/SM) ----------------
__global__ void __launch_bounds__(256, 2) k_spart(const float* __restrict__ vg) {
    extern __shared__ float sm[];
    float* At = sm;            // 128*ATS [i][j]
    float* vt = sm + 128*ATS;  // 128*TS  [i][d]
    int bk = blockIdx.x, p = blockIdx.y;
    int t = threadIdx.x;
    const float* asrc = g_G3b + (size_t)bk*64*NN + p*128;
    for (int x = t; x < 8192; x += 256) {
        int j = x >> 7, i = x & 127;
        At[i*ATS + j] = asrc[(size_t)j*NN + i];
    }
    const float* vsrc = vg + ((size_t)bk*NN + p*128)*DD;
    for (int x = t; x < 8192; x += 256) vt[(x>>6)*TS + (x&63)] = vsrc[x];
    __syncthreads();
    int ig = t >> 4, jg = t & 15;
    float2 R[8];
    mmstd4<128, ATS>(At, vt, R, ig, jg);
    storeR4<64>(g_Sp + ((size_t)bk*NP + p)*4096, R, ig, jg);
}

// ---------------- K10: reduce 32 partials; M = T2 @ S ----------------
__global__ void __launch_bounds__(256) k_mfin() {
    __shared__ float t2T[64*ATS];
    __shared__ float ss[64*TS];
    int bk = blockIdx.x, t = threadIdx.x;
    for (int x = t; x < 4096; x += 256) {
        int r = x >> 6, c = x & 63;
        float s = 0.f;
        #pragma unroll
        for (int p = 0; p < NP; p++) s += g_Sp[((size_t)bk*NP + p)*4096 + x];
        ss[r*TS + c] = s;
        t2T[c*ATS + r] = g_T2[(size_t)bk*4096 + x];
    }
    __syncthreads();
    int ig = t >> 4, jg = t & 15;
    float2 R[8];
    mmstd4<64, ATS>(t2T, ss, R, ig, jg);
    storeR4<64>(g_M + (size_t)bk*4096, R, ig, jg);
}

// ---------------- K11: fused sim1 path (round-13 reg-staged pipeline) ----------------
__global__ void __launch_bounds__(256, 2) k_sim1out(const float* __restrict__ qg,
                          const float* __restrict__ Ws1,
                          const float* __restrict__ Wa1,
                          float* __restrict__ out) {
    extern __shared__ float sm[];
    float* qT  = sm;
    float* kB  = sm + 2304;
    float* raw = sm + 2304 + 4224;
    float* wsa = raw + 8*PS1;
    float* wsb = wsa + 64;
    int b = blockIdx.x >> 7, it = blockIdx.x & 127;
    int i0 = it*32;
    int t = threadIdx.x;
    if (t < 64) { wsa[t] = Ws1[t]; wsb[t] = Wa1[t]; }
    int ig = t >> 4, jg = t & 15;
    {
        float rk[16], rq[8];
        {
            const float* ksrc = g_kl + (size_t)(b*8)*4096;
            const float* qsrc = qg + ((size_t)(b*8)*NN + i0)*DD;
            #pragma unroll
            for (int s = 0; s < 16; s++) rk[s] = ksrc[t + 256*s];
            #pragma unroll
            for (int s = 0; s < 8; s++) rq[s] = qsrc[t + 256*s];
        }
        for (int h = 0; h < 8; h++) {
            __syncthreads();
            #pragma unroll
            for (int s = 0; s < 16; s++) { int x = t + 256*s; kB[(x&63)*TS + (x>>6)] = rk[s]; }
            #pragma unroll
            for (int s = 0; s < 8; s++)  { int x = t + 256*s; qT[(x&63)*ITS + (x>>6)] = rq[s]; }
            __syncthreads();
            if (h < 7) {
                const float* ksrc = g_kl + (size_t)(b*8 + h + 1)*4096;
                const float* qsrc = qg + ((size_t)(b*8 + h + 1)*NN + i0)*DD;
                #pragma unroll
                for (int s = 0; s < 16; s++) rk[s] = ksrc[t + 256*s];
                #pragma unroll
                for (int s = 0; s < 8; s++) rq[s] = qsrc[t + 256*s];
            }
            float2 R[4];
            #pragma unroll
            for (int u = 0; u < 4; u++) R[u] = make_float2(0.f, 0.f);
            #pragma unroll 4
            for (int k = 0; k < 64; k++) {
                float2 a  = *(const float2*)&qT[k*ITS + 2*ig];
                float2 b0 = *(const float2*)&kB[k*TS + 2*jg];
                float2 b1 = *(const float2*)&kB[k*TS + 2*jg + 32];
                ffma2(R[0], a.x, b0); ffma2(R[1], a.x, b1);
                ffma2(R[2], a.y, b0); ffma2(R[3], a.y, b1);
            }
            float* pl = raw + h*PS1;
            *(float2*)&pl[(2*ig    )*TS + 2*jg]      = R[0];
            *(float2*)&pl[(2*ig    )*TS + 2*jg + 32] = R[1];
            *(float2*)&pl[(2*ig + 1)*TS + 2*jg]      = R[2];
            *(float2*)&pl[(2*ig + 1)*TS + 2*jg + 32] = R[3];
        }
    }
    __syncthreads();
    for (int x = t; x < 1024; x += 256) mix8v<PS1>(raw, wsa, (x>>5)*TS + 2*(x&31));
    __syncthreads();
    {
        int kk = t >> 5, i = t & 31;
        float* row = raw + kk*PS1 + i*TS;
        float mx = -3.4e38f;
        for (int j = 0; j < 64; j++) mx = fmaxf(mx, row[j]);
        float sum = 0.f;
        for (int j = 0; j < 64; j++) { float e = __expf(row[j] - mx); row[j] = e; sum += e; }
        float inv = 1.f / sum;
        for (int j = 0; j < 64; j++) row[j] *= inv;
    }
    __syncthreads();
    for (int x = t; x < 1024; x += 256) mix8v<PS1>(raw, wsb, (x>>5)*TS + 2*(x&31));
    {
        float rm[16];
        {
            const float* msrc = g_M + (size_t)(b*8)*4096;
            #pragma unroll
            for (int s = 0; s < 16; s++) rm[s] = msrc[t + 256*s];
        }
        for (int kk = 0; kk < 8; kk++) {
            __syncthreads();
            #pragma unroll
            for (int s = 0; s < 16; s++) { int x = t + 256*s; kB[(x>>6)*TS + (x&63)] = rm[s]; }
            __syncthreads();
            if (kk < 7) {
                const float* msrc = g_M + (size_t)(b*8 + kk + 1)*4096;
                #pragma unroll
                for (int s = 0; s < 16; s++) rm[s] = msrc[t + 256*s];
            }
            const float* pl = raw + kk*PS1;
            float2 R[4];
            #pragma unroll
            for (int u = 0; u < 4; u++) R[u] = make_float2(0.f, 0.f);
            #pragma unroll 4
            for (int k = 0; k < 64; k++) {
                float a0 = pl[(2*ig    )*TS + k];
                float a1 = pl[(2*ig + 1)*TS + k];
                float2 b0 = *(const float2*)&kB[k*TS + 2*jg];
                float2 b1 = *(const float2*)&kB[k*TS + 2*jg + 32];
                ffma2(R[0], a0, b0); ffma2(R[1], a0, b1);
                ffma2(R[2], a1, b0); ffma2(R[3], a1, b1);
            }
            size_t ob = ((size_t)(b*8 + kk)*NN + i0)*DD;
            *(float2*)&out[ob + (size_t)(2*ig    )*DD + 2*jg]      = R[0];
            *(float2*)&out[ob + (size_t)(2*ig    )*DD + 2*jg + 32] = R[1];
            *(float2*)&out[ob + (size_t)(2*ig + 1)*DD + 2*jg]      = R[2];
            *(float2*)&out[ob + (size_t)(2*ig + 1)*DD + 2*jg + 32] = R[3];
        }
    }
}

// ---------------- K12: residual conv (8-row tiles, 2 CTA/SM, RMW on out) ----------------
__device__ __forceinline__ void ffma2v(float2& a, const float2 b, const float2 c) {
    asm("fma.rn.f32x2 %0, %1, %2, %0;"
        : "+l"(reinterpret_cast<unsigned long long&>(a))
        : "l"(reinterpret_cast<const unsigned long long&>(b)),
          "l"(reinterpret_cast<const unsigned long long&>(c)));
}
__global__ void __launch_bounds__(256, 2) k_conv(const float* __restrict__ vg,
                                                 const float* __restrict__ cw,
                                                 float* __restrict__ out) {
    extern __shared__ float sm[];
    float2* vv2 = (float2*)sm;
    float* ws = sm + 20480;
    int b = blockIdx.x >> 9, nt = blockIdx.x & 511;
    int n0 = nt*8;
    int t = threadIdx.x;
    const float2* vg2 = (const float2*)vg;
    for (int x = t; x < 10240; x += 256) {
        int h = x / 1280, rem = x - h*1280;
        int i = rem >> 5, dp = rem & 31;
        int na = n0 - 16 + i;
        float2 val = make_float2(0.f, 0.f);
        if (na >= 0 && na < NN) val = vg2[((size_t)(b*8 + h)*NN + na)*32 + dp];
        vv2[h*1280 + i*32 + dp] = val;
    }
    for (int x = t; x < 2112; x += 256) ws[x] = cw[x];
    __syncthreads();
    int k = t >> 5, dp = t & 31;
    float2 acc[8];
    #pragma unroll
    for (int n = 0; n < 8; n++) acc[n] = make_float2(0.f, 0.f);
    float2 vr[40];
    for (int h = 0; h < 8; h++) {
        #pragma unroll
        for (int i = 0; i < 40; i++) vr[i] = vv2[h*1280 + i*32 + dp];
        const float* wrow = ws + k*264 + h*33;
        #pragma unroll
        for (int tt = 0; tt < 33; tt++) {
            float2 w2 = make_float2(wrow[tt], wrow[tt]);
            #pragma unroll
            for (int n = 0; n < 8; n++) ffma2v(acc[n], w2, vr[n + tt]);
        }
    }
    float2* op = (float2*)out + ((size_t)(b*8 + k)*NN + n0)*32 + dp;
    #pragma unroll
    for (int n = 0; n < 8; n++) {
        float2 cur = op[(size_t)n*32];
        cur.x += acc[n].x; cur.y += acc[n].y;
        op[(size_t)n*32] = cur;
    }
}

// ---------------- launch ----------------
extern "C" void kernel_launch(void* const* d_in, const int* in_sizes, int n_in,
                              void* d_out, int out_size) {
    const float* q   = (const float*)d_in[0];
    const float* k   = (const float*)d_in[1];
    const float* v   = (const float*)d_in[2];
    const float* Ws1 = (const float*)d_in[3];
    const float* Ws2 = (const float*)d_in[4];
    const float* Ws3 = (const float*)d_in[5];
    const float* Wa1 = (const float*)d_in[6];
    const float* Wa2 = (const float*)d_in[7];
    const float* Wa3 = (const float*)d_in[8];
    const float* cw  = (const float*)d_in[9];
    float* out = (float*)d_out;

    const int SMEM_PINV = 16896*4;
    const int SMEM_SIM3 = (4352 + 2304 + 8*PS3 + 64)*4;
    const int SMEM_SIM1 = (2304 + 4224 + 8*PS1 + 128)*4;
    const int SMEM_SPART = (128*ATS + 128*TS)*4;
    const int SMEM_CONV = (20480 + 2112)*4;
    cudaFuncSetAttribute(k_pinv,   cudaFuncAttributeMaxDynamicSharedMemorySize, SMEM_PINV);
    cudaFuncSetAttribute(k_sim3,   cudaFuncAttributeMaxDynamicSharedMemorySize, SMEM_SIM3);
    cudaFuncSetAttribute(k_spart,  cudaFuncAttributeMaxDynamicSharedMemorySize, SMEM_SPART);
    cudaFuncSetAttribute(k_sim1out,cudaFuncAttributeMaxDynamicSharedMemorySize, SMEM_SIM1);
    cudaFuncSetAttribute(k_conv,   cudaFuncAttributeMaxDynamicSharedMemorySize, SMEM_CONV);

    k_landmarks<<<dim3(64, 16), 256>>>(q, k);
    k_sim2dots<<<64, 512>>>();
    k_sim2mix<<<64, 512>>>(Ws2);
    k_pinv<<<64, 256, SMEM_PINV>>>();
    k_mixT2<<<128, 256>>>(Wa2);
    k_sim3<<<1024, 256, SMEM_SIM3>>>(k, Ws3);
    k_rowstat<<<4096, 256>>>();
    k_a3norm<<<dim3(256, 8), 256>>>(Wa3);
    k_spart<<<dim3(64, 32), 256, SMEM_SPART>>>(v);
    k_mfin<<<64, 256>>>();
    k_sim1out<<<1024, 256, SMEM_SIM1>>>(q, Ws1, Wa1, out);
    k_conv<<<4096, 256, SMEM_CONV>>>(v, cw, out);
}